// round 15
// baseline (speedup 1.0000x reference)
#include <cuda_runtime.h>
#include <cuda_fp16.h>
#include <cstdint>
#include <math.h>

#define BATCH 8
#define SEQ   1024
#define CH    768
#define NH    12
#define HD    64
#define BH    (BATCH*NH)   /* 96 */

// ===================== scratch (__device__ globals) =======================
__device__ float g_qkv   [(size_t)BATCH*SEQ*3*CH];   // fp32 qkv
__device__ float g_scores[(size_t)BH*SEQ*SEQ];       // fp32 raw scores
__device__ float g_pmax  [(size_t)BH*SEQ*8];         // per-tile row max
__device__ float g_psum  [(size_t)BH*SEQ*8];         // per-tile row sumexp
__device__ float g_rowM  [(size_t)BH*SEQ];
__device__ float g_rowI  [(size_t)BH*SEQ];

#define H16_BUF(name, elems) __device__ uint4 name[(size_t)(elems)/8]
H16_BUF(g_xh, 6291456);       H16_BUF(g_xl, 6291456);        // x split [8192,768]
H16_BUF(g_wqkvTh, 1769472);   H16_BUF(g_wqkvTl, 1769472);    // w_qkv^T [2304,768]
H16_BUF(g_wprojTh, 589824);   H16_BUF(g_wprojTl, 589824);    // w_proj^T [768,768]
H16_BUF(g_qh, 6291456);       H16_BUF(g_ql, 6291456);        // q [BH,1024,64]
H16_BUF(g_kh, 6291456);       H16_BUF(g_kl, 6291456);        // k [BH,1024,64]
H16_BUF(g_vTh, 6291456);      H16_BUF(g_vTl, 6291456);       // v^T [BH,64,1024]
H16_BUF(g_hh, 6291456);       H16_BUF(g_hl, 6291456);        // heads split [8192,768]

// ===================== PTX helpers (sm_80-portable only) ==================
__device__ __forceinline__ uint32_t smem_u32(const void* p){
    uint32_t a;
    asm("{ .reg .u64 t; cvta.to.shared.u64 t, %1; cvt.u32.u64 %0, t; }" : "=r"(a) : "l"(p));
    return a;
}
__device__ __forceinline__ void cp16(uint32_t dst, const void* src){
    asm volatile("cp.async.cg.shared.global [%0], [%1], 16;" :: "r"(dst), "l"(src));
}
#define CP_COMMIT() asm volatile("cp.async.commit_group;" ::: "memory")
#define CP_WAIT(n)  asm volatile("cp.async.wait_group %0;" :: "n"(n) : "memory")

#define LDSM4(r0,r1,r2,r3,a) \
    asm volatile("ldmatrix.sync.aligned.m8n8.x4.shared.b16 {%0,%1,%2,%3}, [%4];" \
        : "=r"(r0),"=r"(r1),"=r"(r2),"=r"(r3) : "r"(a))

#define MMA16816(c, a, b0, b1) \
    asm volatile("mma.sync.aligned.m16n8k16.row.col.f32.f16.f16.f32 " \
        "{%0,%1,%2,%3},{%4,%5,%6,%7},{%8,%9},{%0,%1,%2,%3};" \
        : "+f"((c)[0]),"+f"((c)[1]),"+f"((c)[2]),"+f"((c)[3]) \
        : "r"((a)[0]),"r"((a)[1]),"r"((a)[2]),"r"((a)[3]), "r"(b0),"r"(b1))

__device__ __forceinline__ void split1(float v, __half& h, __half& l){
    h = __float2half_rn(v);
    l = __float2half_rn(v - __half2float(h));
}

// ===================== mma.sync fp16 split GEMM ===========================
// C = alpha*(A) @ (B)^T (+bias) with hi/lo error splits.
// TERMS=3: AhBh + AhBl + AlBh.  TERMS=2: Ah(Bh+Bl) (A-lo dropped; A-lo
// tiles not even loaded).
// 3-stage cp.async pipeline, XOR-swizzled 64B-row tiles, 2 CTAs/SM,
// one __syncthreads per iteration.
// STATS: additionally emit per-tile row softmax partials (max, sumexp).
template<int BN, int WROWS, int WCOLS, int STATS, int TERMS>
__global__ void __launch_bounds__(256, 2) gemm_mma(
    int K,
    const __half* __restrict__ Ah, const __half* __restrict__ Al, int lda, long long sA,
    const __half* __restrict__ Bh, const __half* __restrict__ Bl, int ldb, long long sB,
    float* __restrict__ C, int ldc, long long sC,
    float alpha, const float* __restrict__ bias,
    float* __restrict__ pm, float* __restrict__ ps)
{
    constexpr int BM = 128, BK = 32, S = 3;
    constexpr int WM = BM / WROWS, WN = BN / WCOLS;
    constexpr int MI = WM / 16, NI = WN / 8;
    constexpr uint32_t ATILE_B = BM * 64;               // bytes (64B per row, no pad)
    constexpr uint32_t BTILE_B = BN * 64;
    constexpr uint32_t STAGE_B = 2*ATILE_B + 2*BTILE_B; // 32768 for BN=128

    extern __shared__ char sm[];
    const uint32_t sb = smem_u32(sm);

    const int tid = threadIdx.x;
    const int lane = tid & 31, wid = tid >> 5;
    const int wr = wid / WCOLS, wc = wid % WCOLS;
    const int lrow = lane & 15, lh = lane >> 4;         // col-chunk half (0/1)

    const long long bz = blockIdx.z;
    const __half* Aht = Ah + bz*sA + (long long)blockIdx.y*BM*lda;
    const __half* Alt = Al + bz*sA + (long long)blockIdx.y*BM*lda;
    const __half* Bht = Bh + bz*sB + (long long)blockIdx.x*BN*ldb;
    const __half* Blt = Bl + bz*sB + (long long)blockIdx.x*BN*ldb;
    C += bz*sC + (long long)blockIdx.y*BM*ldc + (long long)blockIdx.x*BN;

    float acc[MI][NI][4];
    #pragma unroll
    for (int mi=0;mi<MI;mi++)
        #pragma unroll
        for (int ni=0;ni<NI;ni++)
            #pragma unroll
            for (int r=0;r<4;r++) acc[mi][ni][r]=0.f;

    const int NC = K >> 5;

    // XOR swizzle: 16B chunk kc within a 64B row -> kc ^ ((row>>1)&3)
    auto load_stage = [&](int chunk, int s){
        if (chunk < NC){
            const int k0 = chunk << 5;
            const uint32_t base = sb + (uint32_t)s*STAGE_B;
            #pragma unroll
            for (int j=0;j<2;j++){
                int id = tid + j*256, row = id >> 2, kc = id & 3;
                uint32_t sw = (uint32_t)(row*64) + (uint32_t)((kc ^ ((row>>1)&3)) << 4);
                const size_t go = (size_t)row*lda + k0 + kc*8;
                cp16(base + sw, Aht + go);
                if (TERMS == 3) cp16(base + ATILE_B + sw, Alt + go);
            }
            #pragma unroll
            for (int j=0;j<BN/64;j++){
                int id = tid + j*256, row = id >> 2, kc = id & 3;
                uint32_t sw = (uint32_t)(row*64) + (uint32_t)((kc ^ ((row>>1)&3)) << 4);
                const size_t go = (size_t)row*ldb + k0 + kc*8;
                cp16(base + 2*ATILE_B + sw, Bht + go);
                cp16(base + 2*ATILE_B + BTILE_B + sw, Blt + go);
            }
        }
        CP_COMMIT();
    };

    auto compute_stage = [&](int s){
        const uint32_t base = sb + (uint32_t)s*STAGE_B;
        #pragma unroll
        for (int k16=0;k16<2;k16++){
            const int cA = k16*2 + lh;                  // 16B chunk requested
            uint32_t ah[MI][4], al[MI][4];
            #pragma unroll
            for (int mi=0;mi<MI;mi++){
                int row = wr*WM + mi*16 + lrow;
                uint32_t a = base + (uint32_t)(row*64) + (uint32_t)((cA ^ ((row>>1)&3)) << 4);
                LDSM4(ah[mi][0],ah[mi][1],ah[mi][2],ah[mi][3], a);
                if (TERMS == 3){
                    LDSM4(al[mi][0],al[mi][1],al[mi][2],al[mi][3], a + ATILE_B);
                }
            }
            uint32_t bh[NI][2], bl[NI][2];
            #pragma unroll
            for (int p=0;p<NI/2;p++){
                int row = wc*WN + p*16 + lrow;
                uint32_t a = base + 2*ATILE_B + (uint32_t)(row*64) + (uint32_t)((cA ^ ((row>>1)&3)) << 4);
                uint32_t r0,r1,r2,r3;
                LDSM4(r0,r1,r2,r3, a);
                bh[2*p][0]=r0; bh[2*p][1]=r2; bh[2*p+1][0]=r1; bh[2*p+1][1]=r3;
                LDSM4(r0,r1,r2,r3, a + BTILE_B);
                bl[2*p][0]=r0; bl[2*p][1]=r2; bl[2*p+1][0]=r1; bl[2*p+1][1]=r3;
            }
            #pragma unroll
            for (int mi=0;mi<MI;mi++)
                #pragma unroll
                for (int ni=0;ni<NI;ni++){
                    MMA16816(acc[mi][ni], ah[mi], bh[ni][0], bh[ni][1]);
                    MMA16816(acc[mi][ni], ah[mi], bl[ni][0], bl[ni][1]);
                    if (TERMS == 3)
                        MMA16816(acc[mi][ni], al[mi], bh[ni][0], bh[ni][1]);
                }
        }
    };

    // prologue: chunks 0,1 into stages 0,1
    load_stage(0, 0);
    load_stage(1, 1);
    int s_cur = 0, s_nxt = 2;
    for (int i=0;i<NC;i++){
        CP_WAIT(1);                 // all but most-recent group done -> chunk i resident
        __syncthreads();            // all warps done with stage s_nxt's old contents
        load_stage(i+2, s_nxt);     // overlaps compute of chunks i and i+1
        compute_stage(s_cur);
        s_cur = (s_cur==S-1) ? 0 : s_cur+1;
        s_nxt = (s_nxt==S-1) ? 0 : s_nxt+1;
    }

    // ---------------- epilogue: C write ----------------
    const float* bp = bias ? (bias + (long long)blockIdx.x*BN) : nullptr;
    #pragma unroll
    for (int mi=0;mi<MI;mi++){
        #pragma unroll
        for (int ni=0;ni<NI;ni++){
            int row = wr*WM + mi*16 + (lane >> 2);
            int col = wc*WN + ni*8 + (lane & 3)*2;
            float2 v0, v1;
            v0.x = alpha*acc[mi][ni][0];
            v0.y = alpha*acc[mi][ni][1];
            v1.x = alpha*acc[mi][ni][2];
            v1.y = alpha*acc[mi][ni][3];
            if (bp){
                float b0 = bp[col], b1 = bp[col+1];
                v0.x += b0; v0.y += b1; v1.x += b0; v1.y += b1;
            }
            *(float2*)(C + (long long)row*ldc + col) = v0;
            *(float2*)(C + (long long)(row+8)*ldc + col) = v1;
        }
    }

    // ---------------- epilogue: softmax partial stats ----------------
    if (STATS){
        __syncthreads();                   // mainloop smem no longer needed
        float* smax = (float*)sm;          // [128][4]
        float* ssum = smax + 512;
        #pragma unroll
        for (int mi=0;mi<MI;mi++){
            #pragma unroll
            for (int rr=0;rr<2;rr++){
                int row_l = wr*WM + mi*16 + rr*8 + (lane>>2);
                float m = -1e30f;
                #pragma unroll
                for (int ni=0;ni<NI;ni++)
                    m = fmaxf(m, fmaxf(alpha*acc[mi][ni][rr*2], alpha*acc[mi][ni][rr*2+1]));
                m = fmaxf(m, __shfl_xor_sync(0xffffffffu, m, 1));
                m = fmaxf(m, __shfl_xor_sync(0xffffffffu, m, 2));
                float s = 0.f;
                #pragma unroll
                for (int ni=0;ni<NI;ni++){
                    s += __expf(alpha*acc[mi][ni][rr*2]   - m);
                    s += __expf(alpha*acc[mi][ni][rr*2+1] - m);
                }
                s += __shfl_xor_sync(0xffffffffu, s, 1);
                s += __shfl_xor_sync(0xffffffffu, s, 2);
                if ((lane&3) == 0){ smax[row_l*4+wc] = m; ssum[row_l*4+wc] = s; }
            }
        }
        __syncthreads();
        if (tid < BM){
            float m = smax[tid*4];
            #pragma unroll
            for (int w=1;w<4;w++) m = fmaxf(m, smax[tid*4+w]);
            float s = 0.f;
            #pragma unroll
            for (int w=0;w<4;w++) s += ssum[tid*4+w]*__expf(smax[tid*4+w]-m);
            size_t o = ((size_t)bz*SEQ + (size_t)blockIdx.y*BM + tid)*8 + blockIdx.x;
            pm[o] = m; ps[o] = s;
        }
    }
}

// ===================== combine tile partials -> row stats =================
__global__ void combine_stats(const float* __restrict__ pm, const float* __restrict__ ps,
                              float* __restrict__ rm, float* __restrict__ ri)
{
    int idx = blockIdx.x*256 + threadIdx.x;     // < BH*SEQ
    const float* p = pm + (size_t)idx*8;
    const float* q = ps + (size_t)idx*8;
    float m = -1e30f;
    #pragma unroll
    for (int t=0;t<8;t++) m = fmaxf(m, p[t]);
    float s = 0.f;
    #pragma unroll
    for (int t=0;t<8;t++) s += q[t]*__expf(p[t]-m);
    rm[idx] = m; ri[idx] = 1.0f/s;
}

// ===================== AV kernel: normalize + split + MMA =================
// reads raw fp32 scores, applies softmax with precomputed row stats,
// writes fp32 attn to d_out, converts attn hi-only (2-term: attn-lo term
// dropped; error ~u/sqrt(3)*|out|, enters only the small `out` output),
// computes attn_h @ (v_h + v_l)^T, writes heads hi/lo in [B,N,C].
__global__ void __launch_bounds__(256, 2) gemm_av(
    const float* __restrict__ A,             // raw scores fp32
    const float* __restrict__ rowM, const float* __restrict__ rowI,
    const __half* __restrict__ Bh_, const __half* __restrict__ Bl_,  // vT
    float* __restrict__ Aout,                // normalized attn (d_out region)
    __half* __restrict__ hh, __half* __restrict__ hl)
{
    constexpr int BM=128, BN=64, BK=32, STRIDE=40;
    constexpr int WCOLS=2, WM=32, WN=32, MI=2, NI=4;
    constexpr int OFF_AF  = 0;           // 128 x 144B  (fp32, 36-float stride)
    constexpr int OFF_AHI = 18432;       // 128 x 80B
    constexpr int OFF_BHI = 28672;       // 64 x 80B
    constexpr int OFF_BLO = 33792;
    constexpr int STAGEB  = 39936;       // bytes per stage (lo-attn region removed)
    constexpr int NC = SEQ / BK;         // 32

    extern __shared__ char sm[];
    const uint32_t sb = smem_u32(sm);

    const int tid = threadIdx.x;
    const int lane = tid & 31, wid = tid >> 5;
    const int wr = wid / WCOLS, wc = wid % WCOLS;
    const int lrow = lane & 15, lhalf = (lane >> 4) * 8;

    const int bh = blockIdx.z;
    const float*  Ag  = A + (size_t)bh*SEQ*SEQ + (size_t)blockIdx.y*BM*SEQ;
    const __half* Bhg = Bh_ + (size_t)bh*HD*SEQ;
    const __half* Blg = Bl_ + (size_t)bh*HD*SEQ;

    const int row_cv = tid >> 1;
    const int cg = (tid & 1) * 16;
    const size_t grow = (size_t)bh*SEQ + blockIdx.y*BM + row_cv;
    const float Mv = rowM[grow];
    const float Iv = rowI[grow];
    float* Ao = Aout + (size_t)bh*SEQ*SEQ + ((size_t)blockIdx.y*BM + row_cv)*SEQ + cg;

    float acc[MI][NI][4];
    #pragma unroll
    for (int mi=0;mi<MI;mi++)
        #pragma unroll
        for (int ni=0;ni<NI;ni++)
            #pragma unroll
            for (int r=0;r<4;r++) acc[mi][ni][r]=0.f;

    auto load_stage = [&](int chunk, int s){
        const int k0 = chunk << 5;
        const uint32_t base = sb + (uint32_t)(s*STAGEB);
        #pragma unroll
        for (int j=0;j<4;j++){
            int id = tid + j*256, row = id >> 3, c = id & 7;
            cp16(base + OFF_AF + (uint32_t)(row*144 + c*16), Ag + (size_t)row*SEQ + k0 + c*4);
        }
        {
            int row = tid >> 2, c = tid & 3;
            uint32_t d = base + OFF_BHI + (uint32_t)(row*80 + c*16);
            const size_t go = (size_t)row*SEQ + k0 + c*8;
            cp16(d, Bhg + go);
            cp16(d + (OFF_BLO-OFF_BHI), Blg + go);
        }
        CP_COMMIT();
    };

    // normalize 32 cols of one row: fp32 smem -> exp -> gmem attn + hi smem
    auto convert = [&](int s, int k0){
        char* base = sm + s*STAGEB;
        const float* src = (const float*)(base + OFF_AF + row_cv*144) + cg;
        #pragma unroll
        for (int q=0;q<2;q++){
            float4 a = *(const float4*)(src + q*8);
            float4 b = *(const float4*)(src + q*8 + 4);
            a.x = __expf(a.x - Mv)*Iv;  a.y = __expf(a.y - Mv)*Iv;
            a.z = __expf(a.z - Mv)*Iv;  a.w = __expf(a.w - Mv)*Iv;
            b.x = __expf(b.x - Mv)*Iv;  b.y = __expf(b.y - Mv)*Iv;
            b.z = __expf(b.z - Mv)*Iv;  b.w = __expf(b.w - Mv)*Iv;
            *(float4*)(Ao + k0 + q*8)     = a;
            *(float4*)(Ao + k0 + q*8 + 4) = b;
            __half2 hv[4];
            hv[0] = __halves2half2(__float2half_rn(a.x), __float2half_rn(a.y));
            hv[1] = __halves2half2(__float2half_rn(a.z), __float2half_rn(a.w));
            hv[2] = __halves2half2(__float2half_rn(b.x), __float2half_rn(b.y));
            hv[3] = __halves2half2(__float2half_rn(b.z), __float2half_rn(b.w));
            *(uint4*)(base + OFF_AHI + (row_cv*STRIDE + cg + q*8)*2) = *(uint4*)hv;
        }
    };

    auto compute_stage = [&](int s){
        const uint32_t base = sb + (uint32_t)(s*STAGEB);
        #pragma unroll
        for (int k16=0;k16<2;k16++){
            uint32_t ah[MI][4];
            #pragma unroll
            for (int mi=0;mi<MI;mi++){
                uint32_t a = base + OFF_AHI + (uint32_t)((wr*WM + mi*16 + lrow)*STRIDE + k16*16 + lhalf)*2;
                LDSM4(ah[mi][0],ah[mi][1],ah[mi][2],ah[mi][3], a);
            }
            uint32_t bh2[NI][2], bl2[NI][2];
            #pragma unroll
            for (int p=0;p<NI/2;p++){
                uint32_t a = base + OFF_BHI + (uint32_t)((wc*WN + p*16 + lrow)*STRIDE + k16*16 + lhalf)*2;
                uint32_t r0,r1,r2,r3;
                LDSM4(r0,r1,r2,r3, a);
                bh2[2*p][0]=r0; bh2[2*p][1]=r2; bh2[2*p+1][0]=r1; bh2[2*p+1][1]=r3;
                LDSM4(r0,r1,r2,r3, a + (OFF_BLO-OFF_BHI));
                bl2[2*p][0]=r0; bl2[2*p][1]=r2; bl2[2*p+1][0]=r1; bl2[2*p+1][1]=r3;
            }
            #pragma unroll
            for (int mi=0;mi<MI;mi++)
                #pragma unroll
                for (int ni=0;ni<NI;ni++){
                    MMA16816(acc[mi][ni], ah[mi], bh2[ni][0], bh2[ni][1]);
                    MMA16816(acc[mi][ni], ah[mi], bl2[ni][0], bl2[ni][1]);
                }
        }
    };

    load_stage(0, 0);
    for (int i=0;i<NC;i++){
        CP_WAIT(0);
        __syncthreads();                 // chunk i resident; buffers free
        convert(i&1, i<<5);
        if (i+1 < NC) load_stage(i+1, (i+1)&1);
        __syncthreads();                 // converted tiles visible
        compute_stage(i&1);
    }

    // epilogue: heads hi/lo directly in [B,N,C]
    const int b = bh / NH, h = bh % NH;
    #pragma unroll
    for (int mi=0;mi<MI;mi++){
        #pragma unroll
        for (int ni=0;ni<NI;ni++){
            int row = wr*WM + mi*16 + (lane >> 2);
            int d = wc*WN + ni*8 + (lane & 3)*2;
            #pragma unroll
            for (int rr=0; rr<2; rr++){
                int n = blockIdx.y*BM + row + rr*8;
                size_t o = ((size_t)b*SEQ + n)*CH + h*HD + d;
                __half h0,l0,h1,l1;
                split1(acc[mi][ni][rr*2+0], h0, l0);
                split1(acc[mi][ni][rr*2+1], h1, l1);
                *(__half2*)(hh + o) = __halves2half2(h0, h1);
                *(__half2*)(hl + o) = __halves2half2(l0, l1);
            }
        }
    }
}

// ===================== split / transpose / reorder ========================
__global__ void split_fp32(const float* __restrict__ src,
                           __half* __restrict__ hi, __half* __restrict__ lo,
                           long long n)
{
    long long i = ((long long)blockIdx.x*blockDim.x + threadIdx.x) * 4;
    if (i >= n) return;
    float4 v = *(const float4*)(src + i);
    __half h, l;
    split1(v.x, h, l); hi[i+0]=h; lo[i+0]=l;
    split1(v.y, h, l); hi[i+1]=h; lo[i+1]=l;
    split1(v.z, h, l); hi[i+2]=h; lo[i+2]=l;
    split1(v.w, h, l); hi[i+3]=h; lo[i+3]=l;
}

// src [R,C] fp32 -> hiT/loT [C,R] half
__global__ void transpose_split(const float* __restrict__ src, int R, int C,
                                __half* __restrict__ hiT, __half* __restrict__ loT)
{
    __shared__ float t[32][33];
    int c0 = blockIdx.x*32, r0 = blockIdx.y*32;
    int x = threadIdx.x, y = threadIdx.y;
    #pragma unroll
    for (int j = 0; j < 32; j += 8)
        t[y+j][x] = src[(long long)(r0+y+j)*C + c0 + x];
    __syncthreads();
    #pragma unroll
    for (int j = 0; j < 32; j += 8){
        float v = t[x][y+j];
        long long o = (long long)(c0+y+j)*R + r0 + x;
        __half h, l; split1(v, h, l);
        hiT[o] = h; loT[o] = l;
    }
}

// g_qkv fp32 [B,N,3C] -> q_hi/lo [BH,N,64], k_hi/lo [BH,N,64], vT_hi/lo [BH,64,N]
__global__ void reorder_qkv_split(__half* __restrict__ qh, __half* __restrict__ ql,
                                  __half* __restrict__ kh, __half* __restrict__ kl,
                                  __half* __restrict__ vh, __half* __restrict__ vl)
{
    long long idx = (long long)blockIdx.x*blockDim.x + threadIdx.x;
    const long long total = (long long)BATCH*SEQ*3*CH;
    if (idx >= total) return;
    int c = (int)(idx % (3*CH));
    long long r = idx / (3*CH);
    int n = (int)(r % SEQ);
    int b = (int)(r / SEQ);
    int which = c / CH;
    int hc = c % CH;
    int h = hc / HD, d = hc % HD;
    long long bh = (long long)b*NH + h;
    __half h16, l16;
    split1(g_qkv[idx], h16, l16);
    if (which == 0){ long long o = (bh*SEQ + n)*HD + d; qh[o]=h16; ql[o]=l16; }
    else if (which == 1){ long long o = (bh*SEQ + n)*HD + d; kh[o]=h16; kl[o]=l16; }
    else { long long o = (bh*HD + d)*SEQ + n; vh[o]=h16; vl[o]=l16; }
}

// ===================== launch =============================================
extern "C" void kernel_launch(void* const* d_in, const int* in_sizes, int n_in,
                              void* d_out, int out_size)
{
    const float* x      = (const float*)d_in[0];   // [8,1024,768]
    const float* w_qkv  = (const float*)d_in[1];   // [768,2304]
    const float* w_proj = (const float*)d_in[2];   // [768,768]
    const float* b_proj = (const float*)d_in[3];   // [768]
    float* out = (float*)d_out;

    float *qkv, *scores, *pmax, *psum, *rowM, *rowI;
    cudaGetSymbolAddress((void**)&qkv,    g_qkv);
    cudaGetSymbolAddress((void**)&scores, g_scores);
    cudaGetSymbolAddress((void**)&pmax,   g_pmax);
    cudaGetSymbolAddress((void**)&psum,   g_psum);
    cudaGetSymbolAddress((void**)&rowM,   g_rowM);
    cudaGetSymbolAddress((void**)&rowI,   g_rowI);
    void *xh,*xl,*wqh,*wql,*wph,*wpl,*qh,*ql,*kh,*kl,*vh,*vl,*hh,*hl;
    cudaGetSymbolAddress(&xh, g_xh);     cudaGetSymbolAddress(&xl, g_xl);
    cudaGetSymbolAddress(&wqh, g_wqkvTh); cudaGetSymbolAddress(&wql, g_wqkvTl);
    cudaGetSymbolAddress(&wph, g_wprojTh); cudaGetSymbolAddress(&wpl, g_wprojTl);
    cudaGetSymbolAddress(&qh, g_qh);     cudaGetSymbolAddress(&ql, g_ql);
    cudaGetSymbolAddress(&kh, g_kh);     cudaGetSymbolAddress(&kl, g_kl);
    cudaGetSymbolAddress(&vh, g_vTh);    cudaGetSymbolAddress(&vl, g_vTl);
    cudaGetSymbolAddress(&hh, g_hh);     cudaGetSymbolAddress(&hl, g_hl);
    #define HF(p) ((__half*)(p))

    // 3-stage swizzled tiles: 3 * 32768 = 98304 B (2 CTAs/SM)
    cudaFuncSetAttribute(gemm_mma<128,2,4,0,2>, cudaFuncAttributeMaxDynamicSharedMemorySize, 98304);
    cudaFuncSetAttribute(gemm_mma<128,2,4,1,3>, cudaFuncAttributeMaxDynamicSharedMemorySize, 98304);
    cudaFuncSetAttribute(gemm_av, cudaFuncAttributeMaxDynamicSharedMemorySize, 79872);

    const long long OUTE  = (long long)BATCH*SEQ*CH;
    const long long ATTNE = (long long)BH*SEQ*SEQ;
    float* attn_dst = ((long long)out_size >= OUTE + ATTNE) ? (out + OUTE) : scores;

    // 1. split x; transpose+split weights
    split_fp32<<<(unsigned)((OUTE/4 + 255)/256), 256>>>(x, HF(xh), HF(xl), OUTE);
    transpose_split<<<dim3(3*CH/32, CH/32), dim3(32,8)>>>(w_qkv, CH, 3*CH, HF(wqh), HF(wql));
    transpose_split<<<dim3(CH/32, CH/32),   dim3(32,8)>>>(w_proj, CH, CH,  HF(wph), HF(wpl));

    // 2. qkv = x @ w_qkv  (2-term; fp32 out)
    gemm_mma<128,2,4,0,2><<<dim3(3*CH/128, (BATCH*SEQ)/128, 1), 256, 98304>>>(
        CH, HF(xh), HF(xl), CH, 0,
        HF(wqh), HF(wql), CH, 0,
        qkv, 3*CH, 0, 1.0f, nullptr, nullptr, nullptr);

    // 3. split into q / k / vT hi/lo (bandwidth-clean reorder)
    {
        long long total = (long long)BATCH*SEQ*3*CH;
        reorder_qkv_split<<<(unsigned)((total + 255)/256), 256>>>(
            HF(qh), HF(ql), HF(kh), HF(kl), HF(vh), HF(vl));
    }

    // 4. scores = (1/8) q @ k^T + per-tile softmax partials (full 3-term:
    //    score error exponentiates into attn, keep max accuracy here)
    gemm_mma<128,2,4,1,3><<<dim3(SEQ/128, SEQ/128, BH), 256, 98304>>>(
        HD, HF(qh), HF(ql), HD, (long long)SEQ*HD,
        HF(kh), HF(kl), HD, (long long)SEQ*HD,
        scores, SEQ, (long long)SEQ*SEQ, 0.125f, nullptr, pmax, psum);

    // 5. combine tile partials -> per-row max / inv-sum
    combine_stats<<<(BH*SEQ)/256, 256>>>(pmax, psum, rowM, rowI);

    // 6. AV: normalize scores on the fly, write attn fp32, compute
    //    attn_h @ (v_h+v_l) (2-term), write heads hi/lo directly
    gemm_av<<<dim3(1, SEQ/128, BH), 256, 79872>>>(
        scores, rowM, rowI, HF(vh), HF(vl), attn_dst, HF(hh), HF(hl));

    // 7. out = heads @ w_proj + b_proj  (2-term)
    gemm_mma<128,2,4,0,2><<<dim3(CH/128, (BATCH*SEQ)/128, 1), 256, 98304>>>(
        CH, HF(hh), HF(hl), CH, 0,
        HF(wph), HF(wpl), CH, 0,
        out, CH, 0, 1.0f, b_proj, nullptr, nullptr);
}

// round 17
// speedup vs baseline: 1.5141x; 1.5141x over previous
#include <cuda_runtime.h>
#include <cuda_fp16.h>
#include <cstdint>
#include <math.h>

#define BATCH 8
#define SEQ   1024
#define CH    768
#define NH    12
#define HD    64
#define BH    (BATCH*NH)   /* 96 */

// ===================== scratch (__device__ globals) =======================
__device__ float g_qkv   [(size_t)BATCH*SEQ*3*CH];   // fp32 qkv
__device__ float g_scores[(size_t)BH*SEQ*SEQ];       // fp32 raw scores
__device__ float g_pmax  [(size_t)BH*SEQ*8];         // per-tile row max
__device__ float g_psum  [(size_t)BH*SEQ*8];         // per-tile row sumexp
__device__ float g_rowM  [(size_t)BH*SEQ];
__device__ float g_rowI  [(size_t)BH*SEQ];

#define H16_BUF(name, elems) __device__ uint4 name[(size_t)(elems)/8]
H16_BUF(g_xh, 6291456);       H16_BUF(g_xl, 6291456);        // x split [8192,768]
H16_BUF(g_wqkvTh, 1769472);   H16_BUF(g_wqkvTl, 1769472);    // w_qkv^T [2304,768]
H16_BUF(g_wprojTh, 589824);   H16_BUF(g_wprojTl, 589824);    // w_proj^T [768,768]
H16_BUF(g_qh, 6291456);       H16_BUF(g_ql, 6291456);        // q [BH,1024,64]
H16_BUF(g_kh, 6291456);       H16_BUF(g_kl, 6291456);        // k [BH,1024,64]
H16_BUF(g_vTh, 6291456);      H16_BUF(g_vTl, 6291456);       // v^T [BH,64,1024]
H16_BUF(g_hh, 6291456);       H16_BUF(g_hl, 6291456);        // heads split [8192,768]

// ===================== PTX helpers (sm_80-portable only) ==================
__device__ __forceinline__ uint32_t smem_u32(const void* p){
    uint32_t a;
    asm("{ .reg .u64 t; cvta.to.shared.u64 t, %1; cvt.u32.u64 %0, t; }" : "=r"(a) : "l"(p));
    return a;
}
__device__ __forceinline__ void cp16(uint32_t dst, const void* src){
    asm volatile("cp.async.cg.shared.global [%0], [%1], 16;" :: "r"(dst), "l"(src));
}
#define CP_COMMIT() asm volatile("cp.async.commit_group;" ::: "memory")
#define CP_WAIT(n)  asm volatile("cp.async.wait_group %0;" :: "n"(n) : "memory")

#define LDSM4(r0,r1,r2,r3,a) \
    asm volatile("ldmatrix.sync.aligned.m8n8.x4.shared.b16 {%0,%1,%2,%3}, [%4];" \
        : "=r"(r0),"=r"(r1),"=r"(r2),"=r"(r3) : "r"(a))

#define MMA16816(c, a, b0, b1) \
    asm volatile("mma.sync.aligned.m16n8k16.row.col.f32.f16.f16.f32 " \
        "{%0,%1,%2,%3},{%4,%5,%6,%7},{%8,%9},{%0,%1,%2,%3};" \
        : "+f"((c)[0]),"+f"((c)[1]),"+f"((c)[2]),"+f"((c)[3]) \
        : "r"((a)[0]),"r"((a)[1]),"r"((a)[2]),"r"((a)[3]), "r"(b0),"r"(b1))

__device__ __forceinline__ void split1(float v, __half& h, __half& l){
    h = __float2half_rn(v);
    l = __float2half_rn(v - __half2float(h));
}

// ===================== mma.sync fp16 split GEMM ===========================
// C = alpha*(A) @ (B)^T (+bias) with hi/lo error splits.
// TERMS=3: AhBh + AhBl + AlBh.  TERMS=2: Ah(Bh+Bl) (A-lo dropped; A-lo
// tiles not even loaded).
// 3-stage cp.async pipeline, XOR-swizzled 64B-row tiles, 2 CTAs/SM,
// one __syncthreads per iteration.
// STATS: additionally emit per-tile row softmax partials (max, sumexp).
template<int BN, int WROWS, int WCOLS, int STATS, int TERMS>
__global__ void __launch_bounds__(256, 2) gemm_mma(
    int K,
    const __half* __restrict__ Ah, const __half* __restrict__ Al, int lda, long long sA,
    const __half* __restrict__ Bh, const __half* __restrict__ Bl, int ldb, long long sB,
    float* __restrict__ C, int ldc, long long sC,
    float alpha, const float* __restrict__ bias,
    float* __restrict__ pm, float* __restrict__ ps)
{
    constexpr int BM = 128, BK = 32, S = 3;
    constexpr int WM = BM / WROWS, WN = BN / WCOLS;
    constexpr int MI = WM / 16, NI = WN / 8;
    constexpr uint32_t ATILE_B = BM * 64;               // bytes (64B per row, no pad)
    constexpr uint32_t BTILE_B = BN * 64;
    constexpr uint32_t STAGE_B = 2*ATILE_B + 2*BTILE_B; // 32768 for BN=128

    extern __shared__ char sm[];
    const uint32_t sb = smem_u32(sm);

    const int tid = threadIdx.x;
    const int lane = tid & 31, wid = tid >> 5;
    const int wr = wid / WCOLS, wc = wid % WCOLS;
    const int lrow = lane & 15, lh = lane >> 4;         // col-chunk half (0/1)

    const long long bz = blockIdx.z;
    const __half* Aht = Ah + bz*sA + (long long)blockIdx.y*BM*lda;
    const __half* Alt = Al + bz*sA + (long long)blockIdx.y*BM*lda;
    const __half* Bht = Bh + bz*sB + (long long)blockIdx.x*BN*ldb;
    const __half* Blt = Bl + bz*sB + (long long)blockIdx.x*BN*ldb;
    C += bz*sC + (long long)blockIdx.y*BM*ldc + (long long)blockIdx.x*BN;

    float acc[MI][NI][4];
    #pragma unroll
    for (int mi=0;mi<MI;mi++)
        #pragma unroll
        for (int ni=0;ni<NI;ni++)
            #pragma unroll
            for (int r=0;r<4;r++) acc[mi][ni][r]=0.f;

    const int NC = K >> 5;

    // XOR swizzle: 16B chunk kc within a 64B row -> kc ^ ((row>>1)&3)
    auto load_stage = [&](int chunk, int s){
        if (chunk < NC){
            const int k0 = chunk << 5;
            const uint32_t base = sb + (uint32_t)s*STAGE_B;
            #pragma unroll
            for (int j=0;j<2;j++){
                int id = tid + j*256, row = id >> 2, kc = id & 3;
                uint32_t sw = (uint32_t)(row*64) + (uint32_t)((kc ^ ((row>>1)&3)) << 4);
                const size_t go = (size_t)row*lda + k0 + kc*8;
                cp16(base + sw, Aht + go);
                if (TERMS == 3) cp16(base + ATILE_B + sw, Alt + go);
            }
            #pragma unroll
            for (int j=0;j<BN/64;j++){
                int id = tid + j*256, row = id >> 2, kc = id & 3;
                uint32_t sw = (uint32_t)(row*64) + (uint32_t)((kc ^ ((row>>1)&3)) << 4);
                const size_t go = (size_t)row*ldb + k0 + kc*8;
                cp16(base + 2*ATILE_B + sw, Bht + go);
                cp16(base + 2*ATILE_B + BTILE_B + sw, Blt + go);
            }
        }
        CP_COMMIT();
    };

    auto compute_stage = [&](int s){
        const uint32_t base = sb + (uint32_t)s*STAGE_B;
        #pragma unroll
        for (int k16=0;k16<2;k16++){
            const int cA = k16*2 + lh;                  // 16B chunk requested
            uint32_t ah[MI][4], al[MI][4];
            #pragma unroll
            for (int mi=0;mi<MI;mi++){
                int row = wr*WM + mi*16 + lrow;
                uint32_t a = base + (uint32_t)(row*64) + (uint32_t)((cA ^ ((row>>1)&3)) << 4);
                LDSM4(ah[mi][0],ah[mi][1],ah[mi][2],ah[mi][3], a);
                if (TERMS == 3){
                    LDSM4(al[mi][0],al[mi][1],al[mi][2],al[mi][3], a + ATILE_B);
                }
            }
            uint32_t bh[NI][2], bl[NI][2];
            #pragma unroll
            for (int p=0;p<NI/2;p++){
                int row = wc*WN + p*16 + lrow;
                uint32_t a = base + 2*ATILE_B + (uint32_t)(row*64) + (uint32_t)((cA ^ ((row>>1)&3)) << 4);
                uint32_t r0,r1,r2,r3;
                LDSM4(r0,r1,r2,r3, a);
                bh[2*p][0]=r0; bh[2*p][1]=r2; bh[2*p+1][0]=r1; bh[2*p+1][1]=r3;
                LDSM4(r0,r1,r2,r3, a + BTILE_B);
                bl[2*p][0]=r0; bl[2*p][1]=r2; bl[2*p+1][0]=r1; bl[2*p+1][1]=r3;
            }
            #pragma unroll
            for (int mi=0;mi<MI;mi++)
                #pragma unroll
                for (int ni=0;ni<NI;ni++){
                    MMA16816(acc[mi][ni], ah[mi], bh[ni][0], bh[ni][1]);
                    MMA16816(acc[mi][ni], ah[mi], bl[ni][0], bl[ni][1]);
                    if (TERMS == 3)
                        MMA16816(acc[mi][ni], al[mi], bh[ni][0], bh[ni][1]);
                }
        }
    };

    // prologue: chunks 0,1 into stages 0,1
    load_stage(0, 0);
    load_stage(1, 1);
    int s_cur = 0, s_nxt = 2;
    for (int i=0;i<NC;i++){
        CP_WAIT(1);                 // all but most-recent group done -> chunk i resident
        __syncthreads();            // all warps done with stage s_nxt's old contents
        load_stage(i+2, s_nxt);     // overlaps compute of chunks i and i+1
        compute_stage(s_cur);
        s_cur = (s_cur==S-1) ? 0 : s_cur+1;
        s_nxt = (s_nxt==S-1) ? 0 : s_nxt+1;
    }

    // ---------------- epilogue: C write ----------------
    const float* bp = bias ? (bias + (long long)blockIdx.x*BN) : nullptr;
    #pragma unroll
    for (int mi=0;mi<MI;mi++){
        #pragma unroll
        for (int ni=0;ni<NI;ni++){
            int row = wr*WM + mi*16 + (lane >> 2);
            int col = wc*WN + ni*8 + (lane & 3)*2;
            float2 v0, v1;
            v0.x = alpha*acc[mi][ni][0];
            v0.y = alpha*acc[mi][ni][1];
            v1.x = alpha*acc[mi][ni][2];
            v1.y = alpha*acc[mi][ni][3];
            if (bp){
                float b0 = bp[col], b1 = bp[col+1];
                v0.x += b0; v0.y += b1; v1.x += b0; v1.y += b1;
            }
            *(float2*)(C + (long long)row*ldc + col) = v0;
            *(float2*)(C + (long long)(row+8)*ldc + col) = v1;
        }
    }

    // ---------------- epilogue: softmax partial stats ----------------
    if (STATS){
        __syncthreads();                   // mainloop smem no longer needed
        float* smax = (float*)sm;          // [128][4]
        float* ssum = smax + 512;
        #pragma unroll
        for (int mi=0;mi<MI;mi++){
            #pragma unroll
            for (int rr=0;rr<2;rr++){
                int row_l = wr*WM + mi*16 + rr*8 + (lane>>2);
                float m = -1e30f;
                #pragma unroll
                for (int ni=0;ni<NI;ni++)
                    m = fmaxf(m, fmaxf(alpha*acc[mi][ni][rr*2], alpha*acc[mi][ni][rr*2+1]));
                m = fmaxf(m, __shfl_xor_sync(0xffffffffu, m, 1));
                m = fmaxf(m, __shfl_xor_sync(0xffffffffu, m, 2));
                float s = 0.f;
                #pragma unroll
                for (int ni=0;ni<NI;ni++){
                    s += __expf(alpha*acc[mi][ni][rr*2]   - m);
                    s += __expf(alpha*acc[mi][ni][rr*2+1] - m);
                }
                s += __shfl_xor_sync(0xffffffffu, s, 1);
                s += __shfl_xor_sync(0xffffffffu, s, 2);
                if ((lane&3) == 0){ smax[row_l*4+wc] = m; ssum[row_l*4+wc] = s; }
            }
        }
        __syncthreads();
        if (tid < BM){
            float m = smax[tid*4];
            #pragma unroll
            for (int w=1;w<4;w++) m = fmaxf(m, smax[tid*4+w]);
            float s = 0.f;
            #pragma unroll
            for (int w=0;w<4;w++) s += ssum[tid*4+w]*__expf(smax[tid*4+w]-m);
            size_t o = ((size_t)bz*SEQ + (size_t)blockIdx.y*BM + tid)*8 + blockIdx.x;
            pm[o] = m; ps[o] = s;
        }
    }
}

// ===================== combine tile partials -> row stats =================
__global__ void combine_stats(const float* __restrict__ pm, const float* __restrict__ ps,
                              float* __restrict__ rm, float* __restrict__ ri)
{
    int idx = blockIdx.x*256 + threadIdx.x;     // < BH*SEQ
    const float* p = pm + (size_t)idx*8;
    const float* q = ps + (size_t)idx*8;
    float m = -1e30f;
    #pragma unroll
    for (int t=0;t<8;t++) m = fmaxf(m, p[t]);
    float s = 0.f;
    #pragma unroll
    for (int t=0;t<8;t++) s += q[t]*__expf(p[t]-m);
    rm[idx] = m; ri[idx] = 1.0f/s;
}

// ===================== AV kernel: normalize + split + MMA =================
// reads raw fp32 scores, applies softmax with precomputed row stats,
// writes fp32 attn to d_out, converts attn hi-only (2-term: attn-lo term
// dropped; error ~u/sqrt(3)*|out|, enters only the small `out` output),
// computes attn_h @ (v_h + v_l)^T, writes heads hi/lo in [B,N,C].
__global__ void __launch_bounds__(256, 2) gemm_av(
    const float* __restrict__ A,             // raw scores fp32
    const float* __restrict__ rowM, const float* __restrict__ rowI,
    const __half* __restrict__ Bh_, const __half* __restrict__ Bl_,  // vT
    float* __restrict__ Aout,                // normalized attn (d_out region)
    __half* __restrict__ hh, __half* __restrict__ hl)
{
    constexpr int BM=128, BN=64, BK=32, STRIDE=40;
    constexpr int WCOLS=2, WM=32, WN=32, MI=2, NI=4;
    constexpr int OFF_AF  = 0;           // 128 x 144B  (fp32, 36-float stride)
    constexpr int OFF_AHI = 18432;       // 128 x 80B
    constexpr int OFF_BHI = 28672;       // 64 x 80B
    constexpr int OFF_BLO = 33792;
    constexpr int STAGEB  = 39936;       // bytes per stage (lo-attn region removed)
    constexpr int NC = SEQ / BK;         // 32

    extern __shared__ char sm[];
    const uint32_t sb = smem_u32(sm);

    const int tid = threadIdx.x;
    const int lane = tid & 31, wid = tid >> 5;
    const int wr = wid / WCOLS, wc = wid % WCOLS;
    const int lrow = lane & 15, lhalf = (lane >> 4) * 8;

    const int bh = blockIdx.z;
    const float*  Ag  = A + (size_t)bh*SEQ*SEQ + (size_t)blockIdx.y*BM*SEQ;
    const __half* Bhg = Bh_ + (size_t)bh*HD*SEQ;
    const __half* Blg = Bl_ + (size_t)bh*HD*SEQ;

    const int row_cv = tid >> 1;
    const int cg = (tid & 1) * 16;
    const size_t grow = (size_t)bh*SEQ + blockIdx.y*BM + row_cv;
    const float Mv = rowM[grow];
    const float Iv = rowI[grow];
    float* Ao = Aout + (size_t)bh*SEQ*SEQ + ((size_t)blockIdx.y*BM + row_cv)*SEQ + cg;

    float acc[MI][NI][4];
    #pragma unroll
    for (int mi=0;mi<MI;mi++)
        #pragma unroll
        for (int ni=0;ni<NI;ni++)
            #pragma unroll
            for (int r=0;r<4;r++) acc[mi][ni][r]=0.f;

    auto load_stage = [&](int chunk, int s){
        const int k0 = chunk << 5;
        const uint32_t base = sb + (uint32_t)(s*STAGEB);
        #pragma unroll
        for (int j=0;j<4;j++){
            int id = tid + j*256, row = id >> 3, c = id & 7;
            cp16(base + OFF_AF + (uint32_t)(row*144 + c*16), Ag + (size_t)row*SEQ + k0 + c*4);
        }
        {
            int row = tid >> 2, c = tid & 3;
            uint32_t d = base + OFF_BHI + (uint32_t)(row*80 + c*16);
            const size_t go = (size_t)row*SEQ + k0 + c*8;
            cp16(d, Bhg + go);
            cp16(d + (OFF_BLO-OFF_BHI), Blg + go);
        }
        CP_COMMIT();
    };

    // normalize 32 cols of one row: fp32 smem -> exp -> gmem attn + hi smem
    auto convert = [&](int s, int k0){
        char* base = sm + s*STAGEB;
        const float* src = (const float*)(base + OFF_AF + row_cv*144) + cg;
        #pragma unroll
        for (int q=0;q<2;q++){
            float4 a = *(const float4*)(src + q*8);
            float4 b = *(const float4*)(src + q*8 + 4);
            a.x = __expf(a.x - Mv)*Iv;  a.y = __expf(a.y - Mv)*Iv;
            a.z = __expf(a.z - Mv)*Iv;  a.w = __expf(a.w - Mv)*Iv;
            b.x = __expf(b.x - Mv)*Iv;  b.y = __expf(b.y - Mv)*Iv;
            b.z = __expf(b.z - Mv)*Iv;  b.w = __expf(b.w - Mv)*Iv;
            *(float4*)(Ao + k0 + q*8)     = a;
            *(float4*)(Ao + k0 + q*8 + 4) = b;
            __half2 hv[4];
            hv[0] = __halves2half2(__float2half_rn(a.x), __float2half_rn(a.y));
            hv[1] = __halves2half2(__float2half_rn(a.z), __float2half_rn(a.w));
            hv[2] = __halves2half2(__float2half_rn(b.x), __float2half_rn(b.y));
            hv[3] = __halves2half2(__float2half_rn(b.z), __float2half_rn(b.w));
            *(uint4*)(base + OFF_AHI + (row_cv*STRIDE + cg + q*8)*2) = *(uint4*)hv;
        }
    };

    auto compute_stage = [&](int s){
        const uint32_t base = sb + (uint32_t)(s*STAGEB);
        #pragma unroll
        for (int k16=0;k16<2;k16++){
            uint32_t ah[MI][4];
            #pragma unroll
            for (int mi=0;mi<MI;mi++){
                uint32_t a = base + OFF_AHI + (uint32_t)((wr*WM + mi*16 + lrow)*STRIDE + k16*16 + lhalf)*2;
                LDSM4(ah[mi][0],ah[mi][1],ah[mi][2],ah[mi][3], a);
            }
            uint32_t bh2[NI][2], bl2[NI][2];
            #pragma unroll
            for (int p=0;p<NI/2;p++){
                uint32_t a = base + OFF_BHI + (uint32_t)((wc*WN + p*16 + lrow)*STRIDE + k16*16 + lhalf)*2;
                uint32_t r0,r1,r2,r3;
                LDSM4(r0,r1,r2,r3, a);
                bh2[2*p][0]=r0; bh2[2*p][1]=r2; bh2[2*p+1][0]=r1; bh2[2*p+1][1]=r3;
                LDSM4(r0,r1,r2,r3, a + (OFF_BLO-OFF_BHI));
                bl2[2*p][0]=r0; bl2[2*p][1]=r2; bl2[2*p+1][0]=r1; bl2[2*p+1][1]=r3;
            }
            #pragma unroll
            for (int mi=0;mi<MI;mi++)
                #pragma unroll
                for (int ni=0;ni<NI;ni++){
                    MMA16816(acc[mi][ni], ah[mi], bh2[ni][0], bh2[ni][1]);
                    MMA16816(acc[mi][ni], ah[mi], bl2[ni][0], bl2[ni][1]);
                }
        }
    };

    load_stage(0, 0);
    for (int i=0;i<NC;i++){
        CP_WAIT(0);
        __syncthreads();                 // chunk i resident; buffers free
        convert(i&1, i<<5);
        if (i+1 < NC) load_stage(i+1, (i+1)&1);
        __syncthreads();                 // converted tiles visible
        compute_stage(i&1);
    }

    // epilogue: heads hi/lo directly in [B,N,C]
    const int b = bh / NH, h = bh % NH;
    #pragma unroll
    for (int mi=0;mi<MI;mi++){
        #pragma unroll
        for (int ni=0;ni<NI;ni++){
            int row = wr*WM + mi*16 + (lane >> 2);
            int d = wc*WN + ni*8 + (lane & 3)*2;
            #pragma unroll
            for (int rr=0; rr<2; rr++){
                int n = blockIdx.y*BM + row + rr*8;
                size_t o = ((size_t)b*SEQ + n)*CH + h*HD + d;
                __half h0,l0,h1,l1;
                split1(acc[mi][ni][rr*2+0], h0, l0);
                split1(acc[mi][ni][rr*2+1], h1, l1);
                *(__half2*)(hh + o) = __halves2half2(h0, h1);
                *(__half2*)(hl + o) = __halves2half2(l0, l1);
            }
        }
    }
}

// ===================== split / transpose / reorder ========================
__global__ void split_fp32(const float* __restrict__ src,
                           __half* __restrict__ hi, __half* __restrict__ lo,
                           long long n)
{
    long long i = ((long long)blockIdx.x*blockDim.x + threadIdx.x) * 4;
    if (i >= n) return;
    float4 v = *(const float4*)(src + i);
    __half h, l;
    split1(v.x, h, l); hi[i+0]=h; lo[i+0]=l;
    split1(v.y, h, l); hi[i+1]=h; lo[i+1]=l;
    split1(v.z, h, l); hi[i+2]=h; lo[i+2]=l;
    split1(v.w, h, l); hi[i+3]=h; lo[i+3]=l;
}

// src [R,C] fp32 -> hiT/loT [C,R] half
__global__ void transpose_split(const float* __restrict__ src, int R, int C,
                                __half* __restrict__ hiT, __half* __restrict__ loT)
{
    __shared__ float t[32][33];
    int c0 = blockIdx.x*32, r0 = blockIdx.y*32;
    int x = threadIdx.x, y = threadIdx.y;
    #pragma unroll
    for (int j = 0; j < 32; j += 8)
        t[y+j][x] = src[(long long)(r0+y+j)*C + c0 + x];
    __syncthreads();
    #pragma unroll
    for (int j = 0; j < 32; j += 8){
        float v = t[x][y+j];
        long long o = (long long)(c0+y+j)*R + r0 + x;
        __half h, l; split1(v, h, l);
        hiT[o] = h; loT[o] = l;
    }
}

// g_qkv fp32 [B,N,3C] -> q_hi/lo [BH,N,64], k_hi/lo [BH,N,64], vT_hi/lo [BH,64,N]
__global__ void reorder_qkv_split(__half* __restrict__ qh, __half* __restrict__ ql,
                                  __half* __restrict__ kh, __half* __restrict__ kl,
                                  __half* __restrict__ vh, __half* __restrict__ vl)
{
    long long idx = (long long)blockIdx.x*blockDim.x + threadIdx.x;
    const long long total = (long long)BATCH*SEQ*3*CH;
    if (idx >= total) return;
    int c = (int)(idx % (3*CH));
    long long r = idx / (3*CH);
    int n = (int)(r % SEQ);
    int b = (int)(r / SEQ);
    int which = c / CH;
    int hc = c % CH;
    int h = hc / HD, d = hc % HD;
    long long bh = (long long)b*NH + h;
    __half h16, l16;
    split1(g_qkv[idx], h16, l16);
    if (which == 0){ long long o = (bh*SEQ + n)*HD + d; qh[o]=h16; ql[o]=l16; }
    else if (which == 1){ long long o = (bh*SEQ + n)*HD + d; kh[o]=h16; kl[o]=l16; }
    else { long long o = (bh*HD + d)*SEQ + n; vh[o]=h16; vl[o]=l16; }
}

// ===================== launch =============================================
extern "C" void kernel_launch(void* const* d_in, const int* in_sizes, int n_in,
                              void* d_out, int out_size)
{
    const float* x      = (const float*)d_in[0];   // [8,1024,768]
    const float* w_qkv  = (const float*)d_in[1];   // [768,2304]
    const float* w_proj = (const float*)d_in[2];   // [768,768]
    const float* b_proj = (const float*)d_in[3];   // [768]
    float* out = (float*)d_out;

    float *qkv, *scores, *pmax, *psum, *rowM, *rowI;
    cudaGetSymbolAddress((void**)&qkv,    g_qkv);
    cudaGetSymbolAddress((void**)&scores, g_scores);
    cudaGetSymbolAddress((void**)&pmax,   g_pmax);
    cudaGetSymbolAddress((void**)&psum,   g_psum);
    cudaGetSymbolAddress((void**)&rowM,   g_rowM);
    cudaGetSymbolAddress((void**)&rowI,   g_rowI);
    void *xh,*xl,*wqh,*wql,*wph,*wpl,*qh,*ql,*kh,*kl,*vh,*vl,*hh,*hl;
    cudaGetSymbolAddress(&xh, g_xh);     cudaGetSymbolAddress(&xl, g_xl);
    cudaGetSymbolAddress(&wqh, g_wqkvTh); cudaGetSymbolAddress(&wql, g_wqkvTl);
    cudaGetSymbolAddress(&wph, g_wprojTh); cudaGetSymbolAddress(&wpl, g_wprojTl);
    cudaGetSymbolAddress(&qh, g_qh);     cudaGetSymbolAddress(&ql, g_ql);
    cudaGetSymbolAddress(&kh, g_kh);     cudaGetSymbolAddress(&kl, g_kl);
    cudaGetSymbolAddress(&vh, g_vTh);    cudaGetSymbolAddress(&vl, g_vTl);
    cudaGetSymbolAddress(&hh, g_hh);     cudaGetSymbolAddress(&hl, g_hl);
    #define HF(p) ((__half*)(p))

    // 3-stage swizzled tiles: 3 * 32768 = 98304 B (2 CTAs/SM)
    cudaFuncSetAttribute(gemm_mma<128,2,4,0,2>, cudaFuncAttributeMaxDynamicSharedMemorySize, 98304);
    cudaFuncSetAttribute(gemm_mma<128,2,4,1,3>, cudaFuncAttributeMaxDynamicSharedMemorySize, 98304);
    cudaFuncSetAttribute(gemm_av, cudaFuncAttributeMaxDynamicSharedMemorySize, 79872);

    const long long OUTE  = (long long)BATCH*SEQ*CH;
    const long long ATTNE = (long long)BH*SEQ*SEQ;
    float* attn_dst = ((long long)out_size >= OUTE + ATTNE) ? (out + OUTE) : scores;

    // 1. split x; transpose+split weights
    split_fp32<<<(unsigned)((OUTE/4 + 255)/256), 256>>>(x, HF(xh), HF(xl), OUTE);
    transpose_split<<<dim3(3*CH/32, CH/32), dim3(32,8)>>>(w_qkv, CH, 3*CH, HF(wqh), HF(wql));
    transpose_split<<<dim3(CH/32, CH/32),   dim3(32,8)>>>(w_proj, CH, CH,  HF(wph), HF(wpl));

    // 2. qkv = x @ w_qkv  (2-term; fp32 out)
    gemm_mma<128,2,4,0,2><<<dim3(3*CH/128, (BATCH*SEQ)/128, 1), 256, 98304>>>(
        CH, HF(xh), HF(xl), CH, 0,
        HF(wqh), HF(wql), CH, 0,
        qkv, 3*CH, 0, 1.0f, nullptr, nullptr, nullptr);

    // 3. split into q / k / vT hi/lo (bandwidth-clean reorder)
    {
        long long total = (long long)BATCH*SEQ*3*CH;
        reorder_qkv_split<<<(unsigned)((total + 255)/256), 256>>>(
            HF(qh), HF(ql), HF(kh), HF(kl), HF(vh), HF(vl));
    }

    // 4. scores = (1/8) q @ k^T + per-tile softmax partials (full 3-term:
    //    score error exponentiates into attn, keep max accuracy here)
    gemm_mma<128,2,4,1,3><<<dim3(SEQ/128, SEQ/128, BH), 256, 98304>>>(
        HD, HF(qh), HF(ql), HD, (long long)SEQ*HD,
        HF(kh), HF(kl), HD, (long long)SEQ*HD,
        scores, SEQ, (long long)SEQ*SEQ, 0.125f, nullptr, pmax, psum);

    // 5. combine tile partials -> per-row max / inv-sum
    combine_stats<<<(BH*SEQ)/256, 256>>>(pmax, psum, rowM, rowI);

    // 6. AV: normalize scores on the fly, write attn fp32, compute
    //    attn_h @ (v_h+v_l) (2-term), write heads hi/lo directly
    gemm_av<<<dim3(1, SEQ/128, BH), 256, 79872>>>(
        scores, rowM, rowI, HF(vh), HF(vl), attn_dst, HF(hh), HF(hl));

    // 7. out = heads @ w_proj + b_proj  (2-term)
    gemm_mma<128,2,4,0,2><<<dim3(CH/128, (BATCH*SEQ)/128, 1), 256, 98304>>>(
        CH, HF(hh), HF(hl), CH, 0,
        HF(wph), HF(wpl), CH, 0,
        out, CH, 0, 1.0f, b_proj, nullptr, nullptr);
}